// round 10
// baseline (speedup 1.0000x reference)
#include <cuda_runtime.h>

#define HD     64
#define VOC    64
#define HALF   32
#define BATCH  128
#define SEQLEN 2048

// ---- scratch tables (device globals; no allocation allowed) ----
__device__ __align__(16) float g_ks[VOC * HALF];
__device__ __align__(16) float g_ke[VOC * HALF];
__device__ __align__(16) float g_inv_s[VOC];
__device__ __align__(16) float g_inv_e[VOC];
__device__ __align__(16) float g_Ds[VOC * VOC];   // D[v1][v2] = ks(v1).ks(v2)
__device__ __align__(16) float g_De[VOC * VOC];   // D[v1][v2] = ke(v1).ke(v2)

// ============================================================================
// Kernel A: per-vocab-id table precompute (h depends only on token id).
// ============================================================================
__global__ void precompute_kernel(
    const float* __restrict__ embed,
    const float* __restrict__ W1, const float* __restrict__ b1,
    const float* __restrict__ W2, const float* __restrict__ b2,
    const float* __restrict__ ln_g, const float* __restrict__ ln_b,
    const float* __restrict__ Ws, const float* __restrict__ bs,
    const float* __restrict__ We, const float* __restrict__ be)
{
    const int v = blockIdx.x;
    const int t = threadIdx.x;

    __shared__ float s_e[HD];
    __shared__ float s_a[2 * HD];
    __shared__ float s_x[HD];
    __shared__ float s_h[HD];
    __shared__ float s_kv[2 * HALF];

    if (t < HD) s_e[t] = embed[v * HD + t];
    __syncthreads();

    {   // hidden = relu(e @ W1 + b1), 128 units, one per thread
        float acc = b1[t];
        #pragma unroll
        for (int d = 0; d < HD; d++)
            acc = fmaf(s_e[d], W1[d * (2 * HD) + t], acc);
        s_a[t] = fmaxf(acc, 0.0f);
    }
    __syncthreads();

    if (t < HD) {   // ff = hidden @ W2 + b2 ; x = e + ff
        float f = b2[t];
        #pragma unroll
        for (int k = 0; k < 2 * HD; k++)
            f = fmaf(s_a[k], W2[k * HD + t], f);
        s_x[t] = s_e[t] + f;
    }
    __syncthreads();

    if (t < HD) {   // LayerNorm (redundant per thread — tiny)
        float mu = 0.0f;
        #pragma unroll
        for (int d = 0; d < HD; d++) mu += s_x[d];
        mu *= (1.0f / HD);
        float var = 0.0f;
        #pragma unroll
        for (int d = 0; d < HD; d++) {
            float dd = s_x[d] - mu;
            var = fmaf(dd, dd, var);
        }
        var *= (1.0f / HD);
        float r = 1.0f / sqrtf(var + 1e-5f);
        s_h[t] = fmaf((s_x[t] - mu) * r, ln_g[t], ln_b[t]);
    }
    __syncthreads();

    if (t < HALF) {             // k_sem = h @ Ws + bs
        float k = bs[t];
        #pragma unroll
        for (int d = 0; d < HD; d++)
            k = fmaf(s_h[d], Ws[d * HALF + t], k);
        g_ks[v * HALF + t] = k;
        s_kv[t] = k;
    } else if (t < 2 * HALF) {  // k_epi = h @ We + be
        const int j = t - HALF;
        float k = be[j];
        #pragma unroll
        for (int d = 0; d < HD; d++)
            k = fmaf(s_h[d], We[d * HALF + j], k);
        g_ke[v * HALF + j] = k;
        s_kv[t] = k;
    }
    __syncthreads();

    if (t == 0) {               // 1/(k.k + 1e-6)
        float den = 1e-6f;
        #pragma unroll
        for (int j = 0; j < HALF; j++) den = fmaf(s_kv[j], s_kv[j], den);
        g_inv_s[v] = 1.0f / den;
    } else if (t == 1) {
        float den = 1e-6f;
        #pragma unroll
        for (int j = 0; j < HALF; j++) den = fmaf(s_kv[HALF + j], s_kv[HALF + j], den);
        g_inv_e[v] = 1.0f / den;
    }
}

// ============================================================================
// Kernel A2: token-pair dot tables D[v1][v2] = k(v1).k(v2) per memory.
// ============================================================================
__global__ void dots_kernel()
{
    const int v1  = blockIdx.x;
    const int tid = threadIdx.x;
    const int v2  = tid & 63;
    const int mem = tid >> 6;

    const float* tab = mem ? g_ke : g_ks;
    float d = 0.0f;
    #pragma unroll
    for (int j = 0; j < HALF; j++)
        d = fmaf(tab[v1 * HALF + j], tab[v2 * HALF + j], d);
    (mem ? g_De : g_Ds)[v1 * VOC + v2] = d;
}

// ============================================================================
// Kernel B: backward adjoint scan, depth-4 token ring, LEA-friendly raw-v
// addressing, fused (kl, Drow) float4 table. Every LDS consumer is >= 1
// iteration behind the load and every address register is >= 1 iteration old.
//
// ctx = sum_t w_t d_t k(v_t),  d_t = Dq[v_t] - S_{t+1}[v_t],
// S_tau[v] = sum_{s>=tau} dd_s D[v_s, v],  dd_s = w_s inv_s d_s.
// S held as 64 scalars (2/lane, Slo/Shi); lookups via shfl lagged 2 iters,
// corrected by the Dbx/Dc terms (lag-1 would put the 26-cyc shfl on the
// same-iteration path — intentionally NOT done).
//
// 128 threads: warp 0 = sem, warp 1 = epi; warps 2-3 preamble-only (exit).
// ============================================================================
__global__ void __launch_bounds__(128, 1) scan_kernel(
    const int* __restrict__ seq,
    const float* __restrict__ Wo,
    const float* __restrict__ bo,
    float* __restrict__ out)
{
    extern __shared__ int smem_raw[];
    int*    s_tokp = smem_raw;                        // 8 pad + 2048 (raw v)
    int*    s_tok  = s_tokp + 8;
    float*  s_D    = (float*)(s_tok + SEQLEN);        // 2 * 4096
    float4* s_T    = (float4*)(s_D + 2 * VOC * VOC);  // 2*64*32 (kl,Drx,Dry,-)
    float2* s_ivdq = (float2*)(s_T + 2 * VOC * HALF); // 2 * 64 (inv, Dq)
    float*  s_ctx  = (float*)(s_ivdq + 2 * VOC);      // 64

    const int b    = blockIdx.x;
    const int tid  = threadIdx.x;
    const int wid  = tid >> 5;
    const int mem  = wid & 1;                 // valid for wid 0,1
    const int lane = tid & 31;

    // ---- preamble: fill shared tables (all 4 warps cooperate) ----
    {
        const int4* seq4 = (const int4*)(seq + b * SEQLEN);
        int4* tok4 = (int4*)s_tok;            // 32B-aligned (8-int pad)
        for (int i = tid; i < SEQLEN / 4; i += 128)
            tok4[i] = seq4[i];                // raw vocab ids
        if (tid < 8) s_tokp[tid] = 0;         // pad: v = 0 (dead ring state)

        float4* D4 = (float4*)s_D;
        const float4* gDs4 = (const float4*)g_Ds;
        const float4* gDe4 = (const float4*)g_De;
        for (int i = tid; i < VOC * VOC / 4; i += 128) {
            D4[i]                 = gDs4[i];
            D4[VOC * VOC / 4 + i] = gDe4[i];
        }
        // fused (kl, Drow) table: T[mem][v][lane]
        for (int i = tid; i < 2 * VOC * HALF; i += 128) {
            const int m = i >> 11;
            const int v = (i >> 5) & 63;
            const int l = i & 31;
            const float  kl = (m ? g_ke : g_ks)[v * HALF + l];
            const float* Dr = (m ? g_De : g_Ds) + v * VOC + 2 * l;
            s_T[i] = make_float4(kl, Dr[0], Dr[1], 0.0f);
        }
    }
    __syncthreads();

    // per-block (inv, Dq): Dq[v] = D[v][vq], vq = query token id
    if (wid < 2) {
        const int vq = s_tok[SEQLEN - 1];
        const float* Dm  = s_D + mem * (VOC * VOC);
        const float* ivg = mem ? g_inv_e : g_inv_s;
        float2* tq = s_ivdq + mem * VOC;
        for (int v = lane; v < VOC; v += 32)
            tq[v] = make_float2(ivg[v], Dm[v * VOC + vq]);
    }
    __syncthreads();

    if (wid >= 2) return;   // preamble helpers done (exited threads satisfy bar)

    // byte-offset bases (token ring holds raw v; all scales are LEA-fusible)
    const char* Db    = (const char*)(s_D + mem * (VOC * VOC)); // + v*256 + v2*4
    const char* Tb    = (const char*)(s_T + mem * (VOC * HALF)) + lane * 16; // + v*512
    const char* ivdqb = (const char*)(s_ivdq + mem * VOC);      // + v*8

    // recency weight, descending: epi w_t = (t+1)/2048; sem w = 1
    const float winc = mem ? (1.0f / 2048.0f) : 0.0f;

    // ---- prologue: state entering iteration t = 2046 ----
    int o0  = s_tok[2046];
    int om1 = s_tok[2045];
    int om2 = s_tok[2044];
    int om3 = s_tok[2043];

    const float2 qa = *(const float2*)(ivdqb + o0 * 8);
    const float2 qb = *(const float2*)(ivdqb + om1 * 8);
    const float4 Ta = *(const float4*)(Tb + o0 * 512);
    const float4 Tbv = *(const float4*)(Tb + om1 * 512);
    const float w0v = mem ? (2047.0f / 2048.0f) : 1.0f;
    const float w1v = mem ? (2046.0f / 2048.0f) : 1.0f;

    float wiv0   = qa.x * w0v;
    float wkl0   = Ta.x * w0v;
    float wiv_m1 = qb.x * w1v;
    float wkl_m1 = Tbv.x * w1v;

    float pre0  = qa.y;          // d_2046 = Dq[v_2046] (S_2048 = 0)
    float Dq_m1 = qb.y;
    float R_m1  = 0.0f;          // S_2048[v_2045] = 0
    float dd_lag = 0.0f;         // dd_2047 = 0

    float Dc  = 0.0f;            // irrelevant (dd_lag = 0)
    float Dbx = 0.0f;            // irrelevant
    float Drow_x  = Ta.y,  Drow_y  = Ta.z;    // row v_2046 (in use at t=2046)
    float Drow_mx = Tbv.y, Drow_my = Tbv.z;   // row v_2045 (in use at t=2045)

    // staging: token t-2 of the first iteration (v_2044)
    float2 q_c = *(const float2*)(ivdqb + om2 * 8);
    float4 T_c = *(const float4*)(Tb + om2 * 512);
    float wt2  = mem ? (2045.0f / 2048.0f) : 1.0f;   // weight for token t-2

    const int* ptok = s_tok + 2042;                  // &tok[t-4] at t = 2046

    float Slo = 0.0f, Shi = 0.0f;
    float ctx = 0.0f;

    #pragma unroll 4
    for (int t = 2046; t >= 0; --t) {
        // (1) token prefetch, no consumer this iteration
        const int om4 = *ptok;
        --ptok;

        // (2) S lookup for token t-2 against pre-update S (= S_{t+1})
        const float sv   = (om2 & 1) ? Shi : Slo;
        const float R_m2 = __shfl_sync(0xffffffffu, sv, om2 >> 1);

        // (3) prefetch for token t-3 (consumed next iteration and later)
        const float2 q_n = *(const float2*)(ivdqb + om3 * 8);
        const float4 T_n = *(const float4*)(Tb + om3 * 512);

        // (4) chain operands for iteration t-1 (consumed next iteration)
        const float Dc_n  = *(const float*)(Db + o0 * 256 + om1 * 4);
        const float Dbx_n = *(const float*)(Db + o0 * 256 + om2 * 4);

        // (5) critical chain: finalize token t
        const float d  = fmaf(-dd_lag, Dc, pre0);    // d_t
        const float dd = d * wiv0;                   // dd_t
        ctx = fmaf(d, wkl0, ctx);

        // (6) pre for token t-1 (off-chain)
        const float A      = Dq_m1 - R_m1;
        const float pre_m1 = fmaf(-dd_lag, Dbx, A);

        // (7) S-table axpy (shfl above read pre-update values)
        Slo = fmaf(dd, Drow_x, Slo);
        Shi = fmaf(dd, Drow_y, Shi);

        // (8) premultiplies for token t-2 from LAST iteration's loads
        const float wiv2 = q_c.x * wt2;
        const float wkl2 = T_c.x * wt2;
        const float Dq2  = q_c.y;
        wt2 -= winc;

        // (9) rotate
        Dc = Dc_n; Dbx = Dbx_n;
        Drow_x = Drow_mx;  Drow_y = Drow_my;
        Drow_mx = T_c.y;   Drow_my = T_c.z;
        pre0 = pre_m1;
        dd_lag = dd;
        Dq_m1 = Dq2;
        R_m1  = R_m2;
        wiv0 = wiv_m1; wiv_m1 = wiv2;
        wkl0 = wkl_m1; wkl_m1 = wkl2;
        q_c = q_n; T_c = T_n;
        o0 = om1; om1 = om2; om2 = om3; om3 = om4;
    }

    s_ctx[mem * HALF + lane] = ctx;
    __syncthreads();

    // out[b] = [ctx_s, ctx_e] @ Wo + bo   (64 threads, one column each)
    {
        float o = bo[tid];
        #pragma unroll
        for (int i = 0; i < 2 * HALF; i++)
            o = fmaf(s_ctx[i], Wo[i * VOC + tid], o);
        out[b * VOC + tid] = o;
    }
}

// ============================================================================
// Launch. Inputs in metadata order:
// 0:seq 1:embed 2:W1 3:b1 4:W2 5:b2 6:ln_g 7:ln_b 8:Ws 9:bs 10:We 11:be 12:Wo 13:bo
// ============================================================================
// Byte-accurate layout accounting (the R9 bug was undercounting s_ivdq):
//   tok pad+ring: (8 + SEQLEN) * 4      =   8224
//   s_D:          2*VOC*VOC * 4         =  32768
//   s_T:          2*VOC*HALF * 16       =  65536
//   s_ivdq:       2*VOC * sizeof(float2)=   1024
//   s_ctx:        VOC * 4               =    256
#define SCAN_SMEM_BYTES ((8 + SEQLEN) * 4 + 2*VOC*VOC*4 + 2*VOC*HALF*16 \
                         + 2*VOC*8 + VOC*4)

extern "C" void kernel_launch(void* const* d_in, const int* in_sizes, int n_in,
                              void* d_out, int out_size)
{
    const int*   seq   = (const int*)  d_in[0];
    const float* embed = (const float*)d_in[1];
    const float* W1    = (const float*)d_in[2];
    const float* b1    = (const float*)d_in[3];
    const float* W2    = (const float*)d_in[4];
    const float* b2    = (const float*)d_in[5];
    const float* ln_g  = (const float*)d_in[6];
    const float* ln_b  = (const float*)d_in[7];
    const float* Ws    = (const float*)d_in[8];
    const float* bs    = (const float*)d_in[9];
    const float* We    = (const float*)d_in[10];
    const float* be    = (const float*)d_in[11];
    const float* Wo    = (const float*)d_in[12];
    const float* bo    = (const float*)d_in[13];

    cudaFuncSetAttribute(scan_kernel,
                         cudaFuncAttributeMaxDynamicSharedMemorySize,
                         SCAN_SMEM_BYTES);

    precompute_kernel<<<VOC, 128>>>(embed, W1, b1, W2, b2, ln_g, ln_b,
                                    Ws, bs, We, be);
    dots_kernel<<<VOC, 128>>>();
    scan_kernel<<<BATCH, 128, SCAN_SMEM_BYTES>>>(seq, Wo, bo, (float*)d_out);
}

// round 11
// speedup vs baseline: 1.1455x; 1.1455x over previous
#include <cuda_runtime.h>

#define HD     64
#define VOC    64
#define HALF   32
#define BATCH  128
#define SEQLEN 2048

// ---- scratch tables (device globals; no allocation allowed) ----
__device__ __align__(16) float g_ks[VOC * HALF];
__device__ __align__(16) float g_ke[VOC * HALF];
__device__ __align__(16) float g_inv_s[VOC];
__device__ __align__(16) float g_inv_e[VOC];
__device__ __align__(16) float g_Ds[VOC * VOC];   // D[v1][v2] = ks(v1).ks(v2)
__device__ __align__(16) float g_De[VOC * VOC];   // D[v1][v2] = ke(v1).ke(v2)

// ============================================================================
// Kernel A: per-vocab-id table precompute (h depends only on token id).
// ============================================================================
__global__ void precompute_kernel(
    const float* __restrict__ embed,
    const float* __restrict__ W1, const float* __restrict__ b1,
    const float* __restrict__ W2, const float* __restrict__ b2,
    const float* __restrict__ ln_g, const float* __restrict__ ln_b,
    const float* __restrict__ Ws, const float* __restrict__ bs,
    const float* __restrict__ We, const float* __restrict__ be)
{
    const int v = blockIdx.x;
    const int t = threadIdx.x;

    __shared__ float s_e[HD];
    __shared__ float s_a[2 * HD];
    __shared__ float s_x[HD];
    __shared__ float s_h[HD];
    __shared__ float s_kv[2 * HALF];

    if (t < HD) s_e[t] = embed[v * HD + t];
    __syncthreads();

    {   // hidden = relu(e @ W1 + b1), 128 units, one per thread
        float acc = b1[t];
        #pragma unroll
        for (int d = 0; d < HD; d++)
            acc = fmaf(s_e[d], W1[d * (2 * HD) + t], acc);
        s_a[t] = fmaxf(acc, 0.0f);
    }
    __syncthreads();

    if (t < HD) {   // ff = hidden @ W2 + b2 ; x = e + ff
        float f = b2[t];
        #pragma unroll
        for (int k = 0; k < 2 * HD; k++)
            f = fmaf(s_a[k], W2[k * HD + t], f);
        s_x[t] = s_e[t] + f;
    }
    __syncthreads();

    if (t < HD) {   // LayerNorm (redundant per thread — tiny)
        float mu = 0.0f;
        #pragma unroll
        for (int d = 0; d < HD; d++) mu += s_x[d];
        mu *= (1.0f / HD);
        float var = 0.0f;
        #pragma unroll
        for (int d = 0; d < HD; d++) {
            float dd = s_x[d] - mu;
            var = fmaf(dd, dd, var);
        }
        var *= (1.0f / HD);
        float r = 1.0f / sqrtf(var + 1e-5f);
        s_h[t] = fmaf((s_x[t] - mu) * r, ln_g[t], ln_b[t]);
    }
    __syncthreads();

    if (t < HALF) {             // k_sem = h @ Ws + bs
        float k = bs[t];
        #pragma unroll
        for (int d = 0; d < HD; d++)
            k = fmaf(s_h[d], Ws[d * HALF + t], k);
        g_ks[v * HALF + t] = k;
        s_kv[t] = k;
    } else if (t < 2 * HALF) {  // k_epi = h @ We + be
        const int j = t - HALF;
        float k = be[j];
        #pragma unroll
        for (int d = 0; d < HD; d++)
            k = fmaf(s_h[d], We[d * HALF + j], k);
        g_ke[v * HALF + j] = k;
        s_kv[t] = k;
    }
    __syncthreads();

    if (t == 0) {               // 1/(k.k + 1e-6)
        float den = 1e-6f;
        #pragma unroll
        for (int j = 0; j < HALF; j++) den = fmaf(s_kv[j], s_kv[j], den);
        g_inv_s[v] = 1.0f / den;
    } else if (t == 1) {
        float den = 1e-6f;
        #pragma unroll
        for (int j = 0; j < HALF; j++) den = fmaf(s_kv[HALF + j], s_kv[HALF + j], den);
        g_inv_e[v] = 1.0f / den;
    }
}

// ============================================================================
// Kernel A2: token-pair dot tables D[v1][v2] = k(v1).k(v2) per memory.
// ============================================================================
__global__ void dots_kernel()
{
    const int v1  = blockIdx.x;
    const int tid = threadIdx.x;
    const int v2  = tid & 63;
    const int mem = tid >> 6;

    const float* tab = mem ? g_ke : g_ks;
    float d = 0.0f;
    #pragma unroll
    for (int j = 0; j < HALF; j++)
        d = fmaf(tab[v1 * HALF + j], tab[v2 * HALF + j], d);
    (mem ? g_De : g_Ds)[v1 * VOC + v2] = d;
}

// ============================================================================
// Kernel B: backward adjoint scan with the query folded into the S state.
//
// S'_tau[v] = S_tau[v] - Dq[v]  makes the recursion HOMOGENEOUS:
//   d_t  = -S'_{t+1}[v_t]
//   dd_t = wiv_t * d_t
//   S'_t = S'_{t+1} + dd_t * D[v_t, :]
//   S'_2048 = -Dq        (query enters only through the initial condition)
//   ctx  = sum_t d_t * wkl_t
// The per-iteration (inv, Dq) load is GONE: inv rides the T table's .w slot,
// Dq is absorbed at init. Per iter: 4 LDS + 1 shfl + 9 FMA.
// S lookups via shfl lagged 2 iters, corrected by two D terms (Dc/Dbx);
// lag-1 would expose the 26-cyc shfl — intentionally NOT done.
//
// 128 threads: warp 0 = sem, warp 1 = epi; warps 2-3 preamble-only (exit).
// ============================================================================
__global__ void __launch_bounds__(128, 1) scan_kernel(
    const int* __restrict__ seq,
    const float* __restrict__ Wo,
    const float* __restrict__ bo,
    float* __restrict__ out)
{
    extern __shared__ int smem_raw[];
    int*    s_tokp = smem_raw;                        // 8 pad + 2048 (raw v)
    int*    s_tok  = s_tokp + 8;
    float*  s_D    = (float*)(s_tok + SEQLEN);        // 2 * 4096
    float4* s_T    = (float4*)(s_D + 2 * VOC * VOC);  // 2*64*32 (kl,Drx,Dry,inv)
    float*  s_ctx  = (float*)(s_T + 2 * VOC * HALF);  // 64

    const int b    = blockIdx.x;
    const int tid  = threadIdx.x;
    const int wid  = tid >> 5;
    const int mem  = wid & 1;                 // valid for wid 0,1
    const int lane = tid & 31;

    // ---- preamble: fill shared tables (all 4 warps cooperate) ----
    {
        const int4* seq4 = (const int4*)(seq + b * SEQLEN);
        int4* tok4 = (int4*)s_tok;            // 32B-aligned (8-int pad)
        for (int i = tid; i < SEQLEN / 4; i += 128)
            tok4[i] = seq4[i];                // raw vocab ids
        if (tid < 8) s_tokp[tid] = 0;         // pad: v = 0 (dead ring state)

        float4* D4 = (float4*)s_D;
        const float4* gDs4 = (const float4*)g_Ds;
        const float4* gDe4 = (const float4*)g_De;
        for (int i = tid; i < VOC * VOC / 4; i += 128) {
            D4[i]                 = gDs4[i];
            D4[VOC * VOC / 4 + i] = gDe4[i];
        }
        // fused table T[mem][v][lane] = (kl, D[v][2l], D[v][2l+1], inv[v])
        for (int i = tid; i < 2 * VOC * HALF; i += 128) {
            const int m = i >> 11;
            const int v = (i >> 5) & 63;
            const int l = i & 31;
            const float  kl = (m ? g_ke : g_ks)[v * HALF + l];
            const float* Dr = (m ? g_De : g_Ds) + v * VOC + 2 * l;
            const float  iv = (m ? g_inv_e : g_inv_s)[v];
            s_T[i] = make_float4(kl, Dr[0], Dr[1], iv);
        }
    }
    __syncthreads();

    if (wid >= 2) return;   // preamble helpers done (exited threads satisfy bar)

    // byte-offset bases (token ring holds raw v; all scales are LEA-fusible)
    const char* Db = (const char*)(s_D + mem * (VOC * VOC)); // + v*256 + v2*4
    const char* Tb = (const char*)(s_T + mem * (VOC * HALF)) + lane * 16; // + v*512

    // recency weight, descending: epi w_t = (t+1)/2048; sem w = 1
    const float winc = mem ? (1.0f / 2048.0f) : 0.0f;

    // ---- prologue: state entering iteration t = 2046 ----
    const int vq = s_tok[SEQLEN - 1];         // query token id
    int o0  = s_tok[2046];
    int om1 = s_tok[2045];
    int om2 = s_tok[2044];
    int om3 = s_tok[2043];

    // S' init: S'_2048[v] = -Dq[v] = -D[v][vq]   (2 entries per lane)
    const char* Dqcol = Db + vq * 4;
    float Slo = -*(const float*)(Dqcol + (2 * lane) * 256);
    float Shi = -*(const float*)(Dqcol + (2 * lane + 1) * 256);

    // pre0 = d_2046 = Dq[v_2046];  R_m1 = S'_2048[v_2045] = -Dq[v_2045]
    float pre0 = *(const float*)(Dqcol + o0 * 256);
    float R_m1 = -*(const float*)(Dqcol + om1 * 256);

    const float4 Ta  = *(const float4*)(Tb + o0 * 512);
    const float4 Tbv = *(const float4*)(Tb + om1 * 512);
    float4 T_c       = *(const float4*)(Tb + om2 * 512);  // token 2044 staging

    const float w0v = mem ? (2047.0f / 2048.0f) : 1.0f;
    const float w1v = mem ? (2046.0f / 2048.0f) : 1.0f;
    float wt2       = mem ? (2045.0f / 2048.0f) : 1.0f;   // token t-2 weight

    float wiv0   = Ta.w * w0v;
    float wkl0   = Ta.x * w0v;
    float wiv_m1 = Tbv.w * w1v;
    float wkl_m1 = Tbv.x * w1v;

    float Drow_x  = Ta.y,  Drow_y  = Ta.z;    // axpy row for token t
    float Drow_mx = Tbv.y, Drow_my = Tbv.z;   // for token t-1

    float dd_lag = 0.0f;     // dd_2047 (nonexistent)
    float Dc  = 0.0f;        // multiplied by dd_lag = 0
    float Dbx = 0.0f;

    const int* ptok = s_tok + 2042;           // &tok[t-4] at t = 2046
    float ctx = 0.0f;

    #pragma unroll 8
    for (int t = 2046; t >= 0; --t) {
        // (1) token prefetch, no consumer this iteration
        const int om4 = *ptok;
        --ptok;

        // (2) S' lookup for token t-2 against pre-update S' (= S'_{t+1})
        const float sv   = (om2 & 1) ? Shi : Slo;
        const float R_m2 = __shfl_sync(0xffffffffu, sv, om2 >> 1);

        // (3) T prefetch for token t-3 (consumed from next iteration on)
        const float4 T_n = *(const float4*)(Tb + om3 * 512);

        // (4) chain operands for iteration t-1 (consumed next iteration)
        const float Dc_n  = *(const float*)(Db + o0 * 256 + om1 * 4);
        const float Dbx_n = *(const float*)(Db + o0 * 256 + om2 * 4);

        // (5) critical chain: finalize token t
        const float d  = fmaf(-dd_lag, Dc, pre0);    // d_t = -S'_{t+1}[v_t]
        const float dd = d * wiv0;                   // dd_t
        ctx = fmaf(d, wkl0, ctx);

        // (6) pre for token t-1 (off-chain): -R - dd_{t+1} D[v_{t+1},v_{t-1}]
        const float pre_m1 = fmaf(-dd_lag, Dbx, -R_m1);

        // (7) S'-table axpy (shfl above read pre-update values)
        Slo = fmaf(dd, Drow_x, Slo);
        Shi = fmaf(dd, Drow_y, Shi);

        // (8) premultiplies for token t-2 from LAST iteration's T load
        const float wiv2 = T_c.w * wt2;
        const float wkl2 = T_c.x * wt2;
        wt2 -= winc;

        // (9) rotate
        Dc = Dc_n; Dbx = Dbx_n;
        Drow_x = Drow_mx;  Drow_y = Drow_my;
        Drow_mx = T_c.y;   Drow_my = T_c.z;
        pre0 = pre_m1;
        dd_lag = dd;
        R_m1  = R_m2;
        wiv0 = wiv_m1; wiv_m1 = wiv2;
        wkl0 = wkl_m1; wkl_m1 = wkl2;
        T_c = T_n;
        o0 = om1; om1 = om2; om2 = om3; om3 = om4;
    }

    s_ctx[mem * HALF + lane] = ctx;
    __syncthreads();

    // out[b] = [ctx_s, ctx_e] @ Wo + bo   (64 threads, one column each)
    {
        float o = bo[tid];
        #pragma unroll
        for (int i = 0; i < 2 * HALF; i++)
            o = fmaf(s_ctx[i], Wo[i * VOC + tid], o);
        out[b * VOC + tid] = o;
    }
}

// ============================================================================
// Launch. Inputs in metadata order:
// 0:seq 1:embed 2:W1 3:b1 4:W2 5:b2 6:ln_g 7:ln_b 8:Ws 9:bs 10:We 11:be 12:Wo 13:bo
// ============================================================================
// Byte-accurate layout:
//   tok pad+ring: (8 + SEQLEN) * 4  =  8224
//   s_D:          2*VOC*VOC * 4     = 32768
//   s_T:          2*VOC*HALF * 16   = 65536
//   s_ctx:        VOC * 4           =   256
#define SCAN_SMEM_BYTES ((8 + SEQLEN) * 4 + 2*VOC*VOC*4 + 2*VOC*HALF*16 + VOC*4)

extern "C" void kernel_launch(void* const* d_in, const int* in_sizes, int n_in,
                              void* d_out, int out_size)
{
    const int*   seq   = (const int*)  d_in[0];
    const float* embed = (const float*)d_in[1];
    const float* W1    = (const float*)d_in[2];
    const float* b1    = (const float*)d_in[3];
    const float* W2    = (const float*)d_in[4];
    const float* b2    = (const float*)d_in[5];
    const float* ln_g  = (const float*)d_in[6];
    const float* ln_b  = (const float*)d_in[7];
    const float* Ws    = (const float*)d_in[8];
    const float* bs    = (const float*)d_in[9];
    const float* We    = (const float*)d_in[10];
    const float* be    = (const float*)d_in[11];
    const float* Wo    = (const float*)d_in[12];
    const float* bo    = (const float*)d_in[13];

    cudaFuncSetAttribute(scan_kernel,
                         cudaFuncAttributeMaxDynamicSharedMemorySize,
                         SCAN_SMEM_BYTES);

    precompute_kernel<<<VOC, 128>>>(embed, W1, b1, W2, b2, ln_g, ln_b,
                                    Ws, bs, We, be);
    dots_kernel<<<VOC, 128>>>();
    scan_kernel<<<BATCH, 128, SCAN_SMEM_BYTES>>>(seq, Wo, bo, (float*)d_out);
}

// round 12
// speedup vs baseline: 1.1894x; 1.0384x over previous
#include <cuda_runtime.h>

#define HD     64
#define VOC    64
#define HALF   32
#define BATCH  128
#define SEQLEN 2048

// ---- scratch tables (device globals; no allocation allowed) ----
__device__ __align__(16) float g_ks[VOC * HALF];
__device__ __align__(16) float g_ke[VOC * HALF];
__device__ __align__(16) float g_inv_s[VOC];
__device__ __align__(16) float g_inv_e[VOC];
__device__ __align__(16) float g_Ds[VOC * VOC];   // D[v1][v2] = ks(v1).ks(v2)
__device__ __align__(16) float g_De[VOC * VOC];   // D[v1][v2] = ke(v1).ke(v2)

typedef unsigned long long u64;

__device__ __forceinline__ u64 mul2(u64 a, u64 b) {
    u64 d;
    asm("mul.rn.f32x2 %0, %1, %2;" : "=l"(d) : "l"(a), "l"(b));
    return d;
}
__device__ __forceinline__ u64 add2(u64 a, u64 b) {
    u64 d;
    asm("add.rn.f32x2 %0, %1, %2;" : "=l"(d) : "l"(a), "l"(b));
    return d;
}
__device__ __forceinline__ u64 pack2(float x, float y) {
    u64 r;
    asm("mov.b64 %0, {%1, %2};" : "=l"(r) : "f"(x), "f"(y));
    return r;
}
__device__ __forceinline__ float2 unpack2(u64 v) {
    float x, y;
    asm("mov.b64 {%0, %1}, %2;" : "=f"(x), "=f"(y) : "l"(v));
    return make_float2(x, y);
}

// ============================================================================
// Kernel A: per-vocab-id table precompute (h depends only on token id).
// ============================================================================
__global__ void precompute_kernel(
    const float* __restrict__ embed,
    const float* __restrict__ W1, const float* __restrict__ b1,
    const float* __restrict__ W2, const float* __restrict__ b2,
    const float* __restrict__ ln_g, const float* __restrict__ ln_b,
    const float* __restrict__ Ws, const float* __restrict__ bs,
    const float* __restrict__ We, const float* __restrict__ be)
{
    const int v = blockIdx.x;
    const int t = threadIdx.x;

    __shared__ float s_e[HD];
    __shared__ float s_a[2 * HD];
    __shared__ float s_x[HD];
    __shared__ float s_h[HD];
    __shared__ float s_kv[2 * HALF];

    if (t < HD) s_e[t] = embed[v * HD + t];
    __syncthreads();

    {   // hidden = relu(e @ W1 + b1), 128 units, one per thread
        float acc = b1[t];
        #pragma unroll
        for (int d = 0; d < HD; d++)
            acc = fmaf(s_e[d], W1[d * (2 * HD) + t], acc);
        s_a[t] = fmaxf(acc, 0.0f);
    }
    __syncthreads();

    if (t < HD) {   // ff = hidden @ W2 + b2 ; x = e + ff
        float f = b2[t];
        #pragma unroll
        for (int k = 0; k < 2 * HD; k++)
            f = fmaf(s_a[k], W2[k * HD + t], f);
        s_x[t] = s_e[t] + f;
    }
    __syncthreads();

    if (t < HD) {   // LayerNorm (redundant per thread — tiny)
        float mu = 0.0f;
        #pragma unroll
        for (int d = 0; d < HD; d++) mu += s_x[d];
        mu *= (1.0f / HD);
        float var = 0.0f;
        #pragma unroll
        for (int d = 0; d < HD; d++) {
            float dd = s_x[d] - mu;
            var = fmaf(dd, dd, var);
        }
        var *= (1.0f / HD);
        float r = 1.0f / sqrtf(var + 1e-5f);
        s_h[t] = fmaf((s_x[t] - mu) * r, ln_g[t], ln_b[t]);
    }
    __syncthreads();

    if (t < HALF) {             // k_sem = h @ Ws + bs
        float k = bs[t];
        #pragma unroll
        for (int d = 0; d < HD; d++)
            k = fmaf(s_h[d], Ws[d * HALF + t], k);
        g_ks[v * HALF + t] = k;
        s_kv[t] = k;
    } else if (t < 2 * HALF) {  // k_epi = h @ We + be
        const int j = t - HALF;
        float k = be[j];
        #pragma unroll
        for (int d = 0; d < HD; d++)
            k = fmaf(s_h[d], We[d * HALF + j], k);
        g_ke[v * HALF + j] = k;
        s_kv[t] = k;
    }
    __syncthreads();

    if (t == 0) {               // 1/(k.k + 1e-6)
        float den = 1e-6f;
        #pragma unroll
        for (int j = 0; j < HALF; j++) den = fmaf(s_kv[j], s_kv[j], den);
        g_inv_s[v] = 1.0f / den;
    } else if (t == 1) {
        float den = 1e-6f;
        #pragma unroll
        for (int j = 0; j < HALF; j++) den = fmaf(s_kv[HALF + j], s_kv[HALF + j], den);
        g_inv_e[v] = 1.0f / den;
    }
}

// ============================================================================
// Kernel A2: token-pair dot tables D[v1][v2] = k(v1).k(v2) per memory.
// ============================================================================
__global__ void dots_kernel()
{
    const int v1  = blockIdx.x;
    const int tid = threadIdx.x;
    const int v2  = tid & 63;
    const int mem = tid >> 6;

    const float* tab = mem ? g_ke : g_ks;
    float d = 0.0f;
    #pragma unroll
    for (int j = 0; j < HALF; j++)
        d = fmaf(tab[v1 * HALF + j], tab[v2 * HALF + j], d);
    (mem ? g_De : g_Ds)[v1 * VOC + v2] = d;
}

// ============================================================================
// Kernel B: backward adjoint scan, lag-1 S' lookup, int4 token refill,
// packed premultiplies. Homogeneous recursion (query folded into S' init):
//   d_t  = -S'_{t+1}[v_t],   dd_t = wiv_t d_t,
//   S'_t = S'_{t+1} + dd_t D[v_t, :],   S'_2048 = -Dq,
//   ctx  = sum_t wkl_t d_t.
// Lag-1: the shfl at iter t fetches S'_{t+1}[v_{t-1}] (pre-axpy); consumed at
// iter t-1 with ONE correction: d_{t-1} = fma(-dd_t, D[v_t,v_{t-1}], -R).
// Iter t=2047 is a dummy (wkl=wiv=0) making the loop exactly 512 groups of 4;
// tokens refill via one int4 LDS per group from a ring 4+ iterations ahead.
//
// 128 threads: warp 0 = sem, warp 1 = epi; warps 2-3 preamble-only (exit).
// ============================================================================
__global__ void __launch_bounds__(128, 1) scan_kernel(
    const int* __restrict__ seq,
    const float* __restrict__ Wo,
    const float* __restrict__ bo,
    float* __restrict__ out)
{
    extern __shared__ int smem_raw[];
    int*        s_tokp = smem_raw;                         // 16 pad + 2048
    int*        s_tok  = s_tokp + 16;
    float*      s_D    = (float*)(s_tok + SEQLEN);         // 2 * 4096
    ulonglong2* s_T    = (ulonglong2*)(s_D + 2 * VOC * VOC); // 2*64*32 entries
    float*      s_ctx  = (float*)(s_T + 2 * VOC * HALF);   // 64

    const int b    = blockIdx.x;
    const int tid  = threadIdx.x;
    const int wid  = tid >> 5;
    const int mem  = wid & 1;                 // valid for wid 0,1
    const int lane = tid & 31;

    // ---- preamble: fill shared tables (all 4 warps cooperate) ----
    {
        const int4* seq4 = (const int4*)(seq + b * SEQLEN);
        int4* tok4 = (int4*)s_tok;            // 64B-aligned
        for (int i = tid; i < SEQLEN / 4; i += 128)
            tok4[i] = seq4[i];                // raw vocab ids
        if (tid < 16) s_tokp[tid] = 0;        // pad: v = 0 (dead ring state)

        float4* D4 = (float4*)s_D;
        const float4* gDs4 = (const float4*)g_Ds;
        const float4* gDe4 = (const float4*)g_De;
        for (int i = tid; i < VOC * VOC / 4; i += 128) {
            D4[i]                 = gDs4[i];
            D4[VOC * VOC / 4 + i] = gDe4[i];
        }
        // fused table T[mem][v][lane] = ((D[v][2l], D[v][2l+1]), (kl, inv))
        u64* Tp = (u64*)s_T;
        for (int i = tid; i < 2 * VOC * HALF; i += 128) {
            const int m = i >> 11;
            const int v = (i >> 5) & 63;
            const int l = i & 31;
            const float  kl = (m ? g_ke : g_ks)[v * HALF + l];
            const float* Dr = (m ? g_De : g_Ds) + v * VOC + 2 * l;
            const float  iv = (m ? g_inv_e : g_inv_s)[v];
            Tp[2 * i]     = pack2(Dr[0], Dr[1]);
            Tp[2 * i + 1] = pack2(kl, iv);
        }
    }
    __syncthreads();

    if (wid >= 2) return;   // preamble helpers done (exited threads satisfy bar)

    // byte-offset bases (token ring holds raw v; scales are LEA-fusible)
    const char* Db = (const char*)(s_D + mem * (VOC * VOC)); // + v*256 + v2*4
    const char* Tb = (const char*)(s_T + mem * (VOC * HALF)) + lane * 16; // + v*512

    // ---- prologue ----
    const int vq = s_tok[SEQLEN - 1];         // query token id
    int o0  = s_tok[2047];                    // = vq (dummy-iter token)
    int om1 = s_tok[2046];
    int om2 = s_tok[2045];
    int om3 = s_tok[2044];

    // S' init: S'_2048[v] = -D[v][vq]   (2 entries per lane)
    const char* Dqcol = Db + vq * 4;
    float Slo = -*(const float*)(Dqcol + (2 * lane) * 256);
    float Shi = -*(const float*)(Dqcol + (2 * lane + 1) * 256);

    const ulonglong2 T46 = *(const ulonglong2*)(Tb + om1 * 512); // v_2046
    ulonglong2       T_c = *(const ulonglong2*)(Tb + om2 * 512); // v_2045 stage

    const float winc = mem ? (1.0f / 2048.0f) : 0.0f;  // w_t = (t+1)/2048 (epi)
    const float w1v  = mem ? (2047.0f / 2048.0f) : 1.0f;
    const float w2v  = mem ? (2046.0f / 2048.0f) : 1.0f;

    float wiv0 = 0.0f, wkl0 = 0.0f;           // token 2047: dummy (zero weight)
    const float2 T46hi = unpack2(T46.y);      // (kl, inv) of v_2046
    float wkl_m1 = T46hi.x * w1v;
    float wiv_m1 = T46hi.y * w1v;

    float Drow_x = 0.0f, Drow_y = 0.0f;       // token 2047 (dd = 0)
    const float2 T46lo = unpack2(T46.x);
    float Drow_mx = T46lo.x, Drow_my = T46lo.y;  // token 2046

    u64 wt2p  = pack2(w2v, w2v);              // weight for token t-2 premul
    const u64 wincn = pack2(-winc, -winc);

    float R_cur = 0.0f, dd_lag = 0.0f, Dc = 0.0f;  // dummy-iter chain state
    float ctx = 0.0f;

    int4 Q  = *(const int4*)(s_tok + 2040);   // tokens [2040..2043]
    int4 Qn = Q;
    const int* qptr = s_tok + 2036;           // next refill: [2036..2039]

#define STEP(INS, LOADQ) do {                                               \
    /* (a) lag-1 S' lookup for token t-1 (pre-axpy = S'_{t+1}) */           \
    const float sv  = (om1 & 1) ? Shi : Slo;                                \
    const float R_n = __shfl_sync(0xffffffffu, sv, om1 >> 1);               \
    if (LOADQ) { Qn = *(const int4*)qptr; qptr -= 4; }                      \
    /* (b) prefetches (consumed >= 1 iteration later) */                    \
    const ulonglong2 T_n = *(const ulonglong2*)(Tb + om3 * 512);            \
    const float Dc_n = *(const float*)(Db + o0 * 256 + om1 * 4);            \
    /* (c) premul for token t-2 (packed) */                                 \
    const u64 wp = mul2(T_c.y, wt2p);                                       \
    wt2p = add2(wt2p, wincn);                                               \
    const float2 wpu = unpack2(wp);        /* (wkl2, wiv2) */               \
    const float2 drn = unpack2(T_c.x);     /* Drow of token t-2 */          \
    /* (d) critical chain: finalize token t */                              \
    const float d  = fmaf(-dd_lag, Dc, -R_cur);                             \
    const float dd = d * wiv0;                                              \
    ctx = fmaf(d, wkl0, ctx);                                               \
    /* (e) S' axpy (shfl above read pre-update values) */                   \
    Slo = fmaf(dd, Drow_x, Slo);                                            \
    Shi = fmaf(dd, Drow_y, Shi);                                            \
    /* (f) rotate */                                                        \
    R_cur = R_n; Dc = Dc_n; dd_lag = dd;                                    \
    wkl0 = wkl_m1; wiv0 = wiv_m1;                                           \
    wkl_m1 = wpu.x; wiv_m1 = wpu.y;                                         \
    Drow_x = Drow_mx; Drow_y = Drow_my;                                     \
    Drow_mx = drn.x;  Drow_my = drn.y;                                      \
    T_c = T_n;                                                              \
    o0 = om1; om1 = om2; om2 = om3; om3 = (INS);                            \
} while (0)

    #pragma unroll 2
    for (int tb = 2047; tb >= 3; tb -= 4) {
        STEP(Q.w, 1);       // token tb     (inserts v_{tb-4})
        STEP(Q.z, 0);       // token tb-1
        STEP(Q.y, 0);       // token tb-2
        STEP(Q.x, 0);       // token tb-3
        Q = Qn;
    }
#undef STEP

    s_ctx[mem * HALF + lane] = ctx;
    __syncthreads();

    // out[b] = [ctx_s, ctx_e] @ Wo + bo   (64 threads, one column each)
    {
        float o = bo[tid];
        #pragma unroll
        for (int i = 0; i < 2 * HALF; i++)
            o = fmaf(s_ctx[i], Wo[i * VOC + tid], o);
        out[b * VOC + tid] = o;
    }
}

// ============================================================================
// Launch. Inputs in metadata order:
// 0:seq 1:embed 2:W1 3:b1 4:W2 5:b2 6:ln_g 7:ln_b 8:Ws 9:bs 10:We 11:be 12:Wo 13:bo
// ============================================================================
// Byte-accurate layout:
//   tok pad+ring: (16 + SEQLEN) * 4 =  8256
//   s_D:          2*VOC*VOC * 4     = 32768
//   s_T:          2*VOC*HALF * 16   = 65536
//   s_ctx:        VOC * 4           =   256
#define SCAN_SMEM_BYTES ((16 + SEQLEN) * 4 + 2*VOC*VOC*4 + 2*VOC*HALF*16 + VOC*4)

extern "C" void kernel_launch(void* const* d_in, const int* in_sizes, int n_in,
                              void* d_out, int out_size)
{
    const int*   seq   = (const int*)  d_in[0];
    const float* embed = (const float*)d_in[1];
    const float* W1    = (const float*)d_in[2];
    const float* b1    = (const float*)d_in[3];
    const float* W2    = (const float*)d_in[4];
    const float* b2    = (const float*)d_in[5];
    const float* ln_g  = (const float*)d_in[6];
    const float* ln_b  = (const float*)d_in[7];
    const float* Ws    = (const float*)d_in[8];
    const float* bs    = (const float*)d_in[9];
    const float* We    = (const float*)d_in[10];
    const float* be    = (const float*)d_in[11];
    const float* Wo    = (const float*)d_in[12];
    const float* bo    = (const float*)d_in[13];

    cudaFuncSetAttribute(scan_kernel,
                         cudaFuncAttributeMaxDynamicSharedMemorySize,
                         SCAN_SMEM_BYTES);

    precompute_kernel<<<VOC, 128>>>(embed, W1, b1, W2, b2, ln_g, ln_b,
                                    Ws, bs, We, be);
    dots_kernel<<<VOC, 128>>>();
    scan_kernel<<<BATCH, 128, SCAN_SMEM_BYTES>>>(seq, Wo, bo, (float*)d_out);
}

// round 13
// speedup vs baseline: 1.2385x; 1.0412x over previous
#include <cuda_runtime.h>

#define HD     64
#define VOC    64
#define HALF   32
#define BATCH  128
#define SEQLEN 2048

// ---- scratch tables (device globals; no allocation allowed) ----
__device__ __align__(16) float g_ks[VOC * HALF];
__device__ __align__(16) float g_ke[VOC * HALF];
__device__ __align__(16) float g_inv_s[VOC];
__device__ __align__(16) float g_inv_e[VOC];
__device__ __align__(16) float g_Ds[VOC * VOC];   // D[v1][v2] = ks(v1).ks(v2)
__device__ __align__(16) float g_De[VOC * VOC];   // D[v1][v2] = ke(v1).ke(v2)

typedef unsigned long long u64;

// fused per-(mem, v, lane) table: ((D[v][2l], D[v][2l+1]), (k[v][l], inv[v]))
__device__ __align__(16) ulonglong2 g_T[2 * VOC * HALF];

__device__ __forceinline__ u64 mul2(u64 a, u64 b) {
    u64 d;
    asm("mul.rn.f32x2 %0, %1, %2;" : "=l"(d) : "l"(a), "l"(b));
    return d;
}
__device__ __forceinline__ u64 add2(u64 a, u64 b) {
    u64 d;
    asm("add.rn.f32x2 %0, %1, %2;" : "=l"(d) : "l"(a), "l"(b));
    return d;
}
__device__ __forceinline__ u64 pack2(float x, float y) {
    u64 r;
    asm("mov.b64 %0, {%1, %2};" : "=l"(r) : "f"(x), "f"(y));
    return r;
}
__device__ __forceinline__ float2 unpack2(u64 v) {
    float x, y;
    asm("mov.b64 {%0, %1}, %2;" : "=f"(x), "=f"(y) : "l"(v));
    return make_float2(x, y);
}

// ============================================================================
// Kernel A: per-vocab-id table precompute (h depends only on token id).
// ============================================================================
__global__ void precompute_kernel(
    const float* __restrict__ embed,
    const float* __restrict__ W1, const float* __restrict__ b1,
    const float* __restrict__ W2, const float* __restrict__ b2,
    const float* __restrict__ ln_g, const float* __restrict__ ln_b,
    const float* __restrict__ Ws, const float* __restrict__ bs,
    const float* __restrict__ We, const float* __restrict__ be)
{
    const int v = blockIdx.x;
    const int t = threadIdx.x;

    __shared__ float s_e[HD];
    __shared__ float s_a[2 * HD];
    __shared__ float s_x[HD];
    __shared__ float s_h[HD];
    __shared__ float s_kv[2 * HALF];

    if (t < HD) s_e[t] = embed[v * HD + t];
    __syncthreads();

    {   // hidden = relu(e @ W1 + b1), 128 units, one per thread
        float acc = b1[t];
        #pragma unroll
        for (int d = 0; d < HD; d++)
            acc = fmaf(s_e[d], W1[d * (2 * HD) + t], acc);
        s_a[t] = fmaxf(acc, 0.0f);
    }
    __syncthreads();

    if (t < HD) {   // ff = hidden @ W2 + b2 ; x = e + ff
        float f = b2[t];
        #pragma unroll
        for (int k = 0; k < 2 * HD; k++)
            f = fmaf(s_a[k], W2[k * HD + t], f);
        s_x[t] = s_e[t] + f;
    }
    __syncthreads();

    if (t < HD) {   // LayerNorm (redundant per thread — tiny)
        float mu = 0.0f;
        #pragma unroll
        for (int d = 0; d < HD; d++) mu += s_x[d];
        mu *= (1.0f / HD);
        float var = 0.0f;
        #pragma unroll
        for (int d = 0; d < HD; d++) {
            float dd = s_x[d] - mu;
            var = fmaf(dd, dd, var);
        }
        var *= (1.0f / HD);
        float r = 1.0f / sqrtf(var + 1e-5f);
        s_h[t] = fmaf((s_x[t] - mu) * r, ln_g[t], ln_b[t]);
    }
    __syncthreads();

    if (t < HALF) {             // k_sem = h @ Ws + bs
        float k = bs[t];
        #pragma unroll
        for (int d = 0; d < HD; d++)
            k = fmaf(s_h[d], Ws[d * HALF + t], k);
        g_ks[v * HALF + t] = k;
        s_kv[t] = k;
    } else if (t < 2 * HALF) {  // k_epi = h @ We + be
        const int j = t - HALF;
        float k = be[j];
        #pragma unroll
        for (int d = 0; d < HD; d++)
            k = fmaf(s_h[d], We[d * HALF + j], k);
        g_ke[v * HALF + j] = k;
        s_kv[t] = k;
    }
    __syncthreads();

    if (t == 0) {               // 1/(k.k + 1e-6)
        float den = 1e-6f;
        #pragma unroll
        for (int j = 0; j < HALF; j++) den = fmaf(s_kv[j], s_kv[j], den);
        g_inv_s[v] = 1.0f / den;
    } else if (t == 1) {
        float den = 1e-6f;
        #pragma unroll
        for (int j = 0; j < HALF; j++) den = fmaf(s_kv[HALF + j], s_kv[HALF + j], den);
        g_inv_e[v] = 1.0f / den;
    }
}

// ============================================================================
// Kernel A2: token-pair dot tables D[v1][v2] = k(v1).k(v2) per memory, plus
// the packed T table the scan consumes directly:
//   T[m][v][l] = ((D[v][2l], D[v][2l+1]), (k_m[v][l], inv_m[v]))
// ============================================================================
__global__ void dots_kernel()
{
    const int v1  = blockIdx.x;
    const int tid = threadIdx.x;
    const int v2  = tid & 63;
    const int mem = tid >> 6;

    __shared__ float s_drow[2][VOC];

    const float* tab = mem ? g_ke : g_ks;
    float d = 0.0f;
    #pragma unroll
    for (int j = 0; j < HALF; j++)
        d = fmaf(tab[v1 * HALF + j], tab[v2 * HALF + j], d);
    (mem ? g_De : g_Ds)[v1 * VOC + v2] = d;
    s_drow[mem][v2] = d;
    __syncthreads();

    // build T entries for row v1 (32 lanes per mem; upper half-threads idle)
    const int l = tid & 63;
    if (l < HALF) {
        const float kl = (mem ? g_ke : g_ks)[v1 * HALF + l];
        const float iv = (mem ? g_inv_e : g_inv_s)[v1];
        ulonglong2 e;
        e.x = pack2(s_drow[mem][2 * l], s_drow[mem][2 * l + 1]);
        e.y = pack2(kl, iv);
        g_T[mem * (VOC * HALF) + v1 * HALF + l] = e;
    }
}

// ============================================================================
// Kernel B: backward adjoint scan, lag-1 S' lookup, int4 token refill,
// packed premultiplies. Homogeneous recursion (query folded into S' init):
//   d_t  = -S'_{t+1}[v_t],   dd_t = wiv_t d_t,
//   S'_t = S'_{t+1} + dd_t D[v_t, :],   S'_2048 = -Dq,
//   ctx  = sum_t wkl_t d_t.
// Lag-1: the shfl at iter t fetches S'_{t+1}[v_{t-1}] (pre-axpy); consumed at
// iter t-1 with ONE correction: d_{t-1} = fma(-dd_t, D[v_t,v_{t-1}], -R).
// Iter t=2047 is a dummy (wkl=wiv=0) making the loop exactly 512 groups of 4;
// tokens refill via one int4 LDS per group from a ring 4+ iterations ahead.
//
// 256 threads: warp 0 = sem, warp 1 = epi; warps 2-7 preamble-only (exit).
// Preamble is now pure wide copies (T prebuilt in dots_kernel).
// ============================================================================
__global__ void __launch_bounds__(256, 1) scan_kernel(
    const int* __restrict__ seq,
    const float* __restrict__ Wo,
    const float* __restrict__ bo,
    float* __restrict__ out)
{
    extern __shared__ int smem_raw[];
    int*        s_tokp = smem_raw;                         // 16 pad + 2048
    int*        s_tok  = s_tokp + 16;
    float*      s_D    = (float*)(s_tok + SEQLEN);         // 2 * 4096
    ulonglong2* s_T    = (ulonglong2*)(s_D + 2 * VOC * VOC); // 2*64*32 entries
    float*      s_ctx  = (float*)(s_T + 2 * VOC * HALF);   // 64

    const int b    = blockIdx.x;
    const int tid  = threadIdx.x;
    const int wid  = tid >> 5;
    const int mem  = wid & 1;                 // valid for wid 0,1
    const int lane = tid & 31;

    // ---- preamble: pure wide copies (8 warps cooperate) ----
    {
        const int4* seq4 = (const int4*)(seq + b * SEQLEN);
        int4* tok4 = (int4*)s_tok;            // 64B-aligned
        #pragma unroll
        for (int i = tid; i < SEQLEN / 4; i += 256)
            tok4[i] = seq4[i];                // raw vocab ids
        if (tid < 16) s_tokp[tid] = 0;        // pad: v = 0 (dead ring state)

        float4* D4 = (float4*)s_D;
        const float4* gDs4 = (const float4*)g_Ds;
        const float4* gDe4 = (const float4*)g_De;
        #pragma unroll
        for (int i = tid; i < VOC * VOC / 4; i += 256) {
            D4[i]                 = gDs4[i];
            D4[VOC * VOC / 4 + i] = gDe4[i];
        }
        #pragma unroll
        for (int i = tid; i < 2 * VOC * HALF; i += 256)
            s_T[i] = g_T[i];
    }
    __syncthreads();

    if (wid >= 2) return;   // preamble helpers done (exited threads satisfy bar)

    // byte-offset bases (token ring holds raw v; scales are LEA-fusible)
    const char* Db = (const char*)(s_D + mem * (VOC * VOC)); // + v*256 + v2*4
    const char* Tb = (const char*)(s_T + mem * (VOC * HALF)) + lane * 16; // + v*512

    // ---- prologue ----
    const int vq = s_tok[SEQLEN - 1];         // query token id
    int o0  = s_tok[2047];                    // = vq (dummy-iter token)
    int om1 = s_tok[2046];
    int om2 = s_tok[2045];
    int om3 = s_tok[2044];

    // S' init: S'_2048[v] = -D[v][vq]   (2 entries per lane)
    const char* Dqcol = Db + vq * 4;
    float Slo = -*(const float*)(Dqcol + (2 * lane) * 256);
    float Shi = -*(const float*)(Dqcol + (2 * lane + 1) * 256);

    const ulonglong2 T46 = *(const ulonglong2*)(Tb + om1 * 512); // v_2046
    ulonglong2       T_c = *(const ulonglong2*)(Tb + om2 * 512); // v_2045 stage

    const float winc = mem ? (1.0f / 2048.0f) : 0.0f;  // w_t = (t+1)/2048 (epi)
    const float w1v  = mem ? (2047.0f / 2048.0f) : 1.0f;
    const float w2v  = mem ? (2046.0f / 2048.0f) : 1.0f;

    float wiv0 = 0.0f, wkl0 = 0.0f;           // token 2047: dummy (zero weight)
    const float2 T46hi = unpack2(T46.y);      // (kl, inv) of v_2046
    float wkl_m1 = T46hi.x * w1v;
    float wiv_m1 = T46hi.y * w1v;

    float Drow_x = 0.0f, Drow_y = 0.0f;       // token 2047 (dd = 0)
    const float2 T46lo = unpack2(T46.x);
    float Drow_mx = T46lo.x, Drow_my = T46lo.y;  // token 2046

    u64 wt2p  = pack2(w2v, w2v);              // weight for token t-2 premul
    const u64 wincn = pack2(-winc, -winc);

    float R_cur = 0.0f, dd_lag = 0.0f, Dc = 0.0f;  // dummy-iter chain state
    float ctx = 0.0f;

    int4 Q  = *(const int4*)(s_tok + 2040);   // tokens [2040..2043]
    int4 Qn = Q;
    const int* qptr = s_tok + 2036;           // next refill: [2036..2039]

#define STEP(INS, LOADQ) do {                                               \
    /* (a) lag-1 S' lookup for token t-1 (pre-axpy = S'_{t+1}) */           \
    const float sv  = (om1 & 1) ? Shi : Slo;                                \
    const float R_n = __shfl_sync(0xffffffffu, sv, om1 >> 1);               \
    if (LOADQ) { Qn = *(const int4*)qptr; qptr -= 4; }                      \
    /* (b) prefetches (consumed >= 1 iteration later) */                    \
    const ulonglong2 T_n = *(const ulonglong2*)(Tb + om3 * 512);            \
    const float Dc_n = *(const float*)(Db + o0 * 256 + om1 * 4);            \
    /* (c) premul for token t-2 (packed) */                                 \
    const u64 wp = mul2(T_c.y, wt2p);                                       \
    wt2p = add2(wt2p, wincn);                                               \
    const float2 wpu = unpack2(wp);        /* (wkl2, wiv2) */               \
    const float2 drn = unpack2(T_c.x);     /* Drow of token t-2 */          \
    /* (d) critical chain: finalize token t */                              \
    const float d  = fmaf(-dd_lag, Dc, -R_cur);                             \
    const float dd = d * wiv0;                                              \
    ctx = fmaf(d, wkl0, ctx);                                               \
    /* (e) S' axpy (shfl above read pre-update values) */                   \
    Slo = fmaf(dd, Drow_x, Slo);                                            \
    Shi = fmaf(dd, Drow_y, Shi);                                            \
    /* (f) rotate */                                                        \
    R_cur = R_n; Dc = Dc_n; dd_lag = dd;                                    \
    wkl0 = wkl_m1; wiv0 = wiv_m1;                                           \
    wkl_m1 = wpu.x; wiv_m1 = wpu.y;                                         \
    Drow_x = Drow_mx; Drow_y = Drow_my;                                     \
    Drow_mx = drn.x;  Drow_my = drn.y;                                      \
    T_c = T_n;                                                              \
    o0 = om1; om1 = om2; om2 = om3; om3 = (INS);                            \
} while (0)

    #pragma unroll 2
    for (int tb = 2047; tb >= 3; tb -= 4) {
        STEP(Q.w, 1);       // token tb     (inserts v_{tb-4})
        STEP(Q.z, 0);       // token tb-1
        STEP(Q.y, 0);       // token tb-2
        STEP(Q.x, 0);       // token tb-3
        Q = Qn;
    }
#undef STEP

    s_ctx[mem * HALF + lane] = ctx;
    __syncthreads();

    // out[b] = [ctx_s, ctx_e] @ Wo + bo   (64 threads, one column each)
    {
        float o = bo[tid];
        #pragma unroll
        for (int i = 0; i < 2 * HALF; i++)
            o = fmaf(s_ctx[i], Wo[i * VOC + tid], o);
        out[b * VOC + tid] = o;
    }
}

// ============================================================================
// Launch. Inputs in metadata order:
// 0:seq 1:embed 2:W1 3:b1 4:W2 5:b2 6:ln_g 7:ln_b 8:Ws 9:bs 10:We 11:be 12:Wo 13:bo
// ============================================================================
// Byte-accurate layout:
//   tok pad+ring: (16 + SEQLEN) * 4 =  8256
//   s_D:          2*VOC*VOC * 4     = 32768
//   s_T:          2*VOC*HALF * 16   = 65536
//   s_ctx:        VOC * 4           =   256
#define SCAN_SMEM_BYTES ((16 + SEQLEN) * 4 + 2*VOC*VOC*4 + 2*VOC*HALF*16 + VOC*4)

extern "C" void kernel_launch(void* const* d_in, const int* in_sizes, int n_in,
                              void* d_out, int out_size)
{
    const int*   seq   = (const int*)  d_in[0];
    const float* embed = (const float*)d_in[1];
    const float* W1    = (const float*)d_in[2];
    const float* b1    = (const float*)d_in[3];
    const float* W2    = (const float*)d_in[4];
    const float* b2    = (const float*)d_in[5];
    const float* ln_g  = (const float*)d_in[6];
    const float* ln_b  = (const float*)d_in[7];
    const float* Ws    = (const float*)d_in[8];
    const float* bs    = (const float*)d_in[9];
    const float* We    = (const float*)d_in[10];
    const float* be    = (const float*)d_in[11];
    const float* Wo    = (const float*)d_in[12];
    const float* bo    = (const float*)d_in[13];

    cudaFuncSetAttribute(scan_kernel,
                         cudaFuncAttributeMaxDynamicSharedMemorySize,
                         SCAN_SMEM_BYTES);

    precompute_kernel<<<VOC, 128>>>(embed, W1, b1, W2, b2, ln_g, ln_b,
                                    Ws, bs, We, be);
    dots_kernel<<<VOC, 128>>>();
    scan_kernel<<<BATCH, 256, SCAN_SMEM_BYTES>>>(seq, Wo, bo, (float*)d_out);
}

// round 14
// speedup vs baseline: 1.3442x; 1.0854x over previous
#include <cuda_runtime.h>

#define HD     64
#define VOC    64
#define HALF   32
#define BATCH  128
#define SEQLEN 2048

// ---- scratch tables (device globals; no allocation allowed) ----
__device__ __align__(16) float g_ks[VOC * HALF];
__device__ __align__(16) float g_ke[VOC * HALF];
__device__ __align__(16) float g_inv_s[VOC];
__device__ __align__(16) float g_inv_e[VOC];
__device__ __align__(16) float g_Ds[VOC * VOC];   // D[v1][v2] = ks(v1).ks(v2)
__device__ __align__(16) float g_De[VOC * VOC];   // D[v1][v2] = ke(v1).ke(v2)

typedef unsigned long long u64;

// fused per-(mem, v, lane) table: ((D[v][2l], D[v][2l+1]), (k[v][l], inv[v]))
__device__ __align__(16) ulonglong2 g_T[2 * VOC * HALF];

__device__ __forceinline__ u64 mul2(u64 a, u64 b) {
    u64 d;
    asm("mul.rn.f32x2 %0, %1, %2;" : "=l"(d) : "l"(a), "l"(b));
    return d;
}
__device__ __forceinline__ u64 add2(u64 a, u64 b) {
    u64 d;
    asm("add.rn.f32x2 %0, %1, %2;" : "=l"(d) : "l"(a), "l"(b));
    return d;
}
__device__ __forceinline__ u64 pack2(float x, float y) {
    u64 r;
    asm("mov.b64 %0, {%1, %2};" : "=l"(r) : "f"(x), "f"(y));
    return r;
}
__device__ __forceinline__ float2 unpack2(u64 v) {
    float x, y;
    asm("mov.b64 {%0, %1}, %2;" : "=f"(x), "=f"(y) : "l"(v));
    return make_float2(x, y);
}

// ============================================================================
// Kernel A: per-vocab-id table precompute (h depends only on token id).
// ============================================================================
__global__ void precompute_kernel(
    const float* __restrict__ embed,
    const float* __restrict__ W1, const float* __restrict__ b1,
    const float* __restrict__ W2, const float* __restrict__ b2,
    const float* __restrict__ ln_g, const float* __restrict__ ln_b,
    const float* __restrict__ Ws, const float* __restrict__ bs,
    const float* __restrict__ We, const float* __restrict__ be)
{
    const int v = blockIdx.x;
    const int t = threadIdx.x;

    __shared__ float s_e[HD];
    __shared__ float s_a[2 * HD];
    __shared__ float s_x[HD];
    __shared__ float s_h[HD];
    __shared__ float s_kv[2 * HALF];

    if (t < HD) s_e[t] = embed[v * HD + t];
    __syncthreads();

    {   // hidden = relu(e @ W1 + b1), 128 units, one per thread
        float acc = b1[t];
        #pragma unroll
        for (int d = 0; d < HD; d++)
            acc = fmaf(s_e[d], W1[d * (2 * HD) + t], acc);
        s_a[t] = fmaxf(acc, 0.0f);
    }
    __syncthreads();

    if (t < HD) {   // ff = hidden @ W2 + b2 ; x = e + ff
        float f = b2[t];
        #pragma unroll
        for (int k = 0; k < 2 * HD; k++)
            f = fmaf(s_a[k], W2[k * HD + t], f);
        s_x[t] = s_e[t] + f;
    }
    __syncthreads();

    if (t < HD) {   // LayerNorm (redundant per thread — tiny)
        float mu = 0.0f;
        #pragma unroll
        for (int d = 0; d < HD; d++) mu += s_x[d];
        mu *= (1.0f / HD);
        float var = 0.0f;
        #pragma unroll
        for (int d = 0; d < HD; d++) {
            float dd = s_x[d] - mu;
            var = fmaf(dd, dd, var);
        }
        var *= (1.0f / HD);
        float r = 1.0f / sqrtf(var + 1e-5f);
        s_h[t] = fmaf((s_x[t] - mu) * r, ln_g[t], ln_b[t]);
    }
    __syncthreads();

    if (t < HALF) {             // k_sem = h @ Ws + bs
        float k = bs[t];
        #pragma unroll
        for (int d = 0; d < HD; d++)
            k = fmaf(s_h[d], Ws[d * HALF + t], k);
        g_ks[v * HALF + t] = k;
        s_kv[t] = k;
    } else if (t < 2 * HALF) {  // k_epi = h @ We + be
        const int j = t - HALF;
        float k = be[j];
        #pragma unroll
        for (int d = 0; d < HD; d++)
            k = fmaf(s_h[d], We[d * HALF + j], k);
        g_ke[v * HALF + j] = k;
        s_kv[t] = k;
    }
    __syncthreads();

    if (t == 0) {               // 1/(k.k + 1e-6)
        float den = 1e-6f;
        #pragma unroll
        for (int j = 0; j < HALF; j++) den = fmaf(s_kv[j], s_kv[j], den);
        g_inv_s[v] = 1.0f / den;
    } else if (t == 1) {
        float den = 1e-6f;
        #pragma unroll
        for (int j = 0; j < HALF; j++) den = fmaf(s_kv[HALF + j], s_kv[HALF + j], den);
        g_inv_e[v] = 1.0f / den;
    }
}

// ============================================================================
// Kernel A2: token-pair dot tables + the packed T table the scan consumes:
//   T[m][v][l] = ((D[v][2l], D[v][2l+1]), (k_m[v][l], inv_m[v]))
// ============================================================================
__global__ void dots_kernel()
{
    const int v1  = blockIdx.x;
    const int tid = threadIdx.x;
    const int v2  = tid & 63;
    const int mem = tid >> 6;

    __shared__ float s_drow[2][VOC];

    const float* tab = mem ? g_ke : g_ks;
    float d = 0.0f;
    #pragma unroll
    for (int j = 0; j < HALF; j++)
        d = fmaf(tab[v1 * HALF + j], tab[v2 * HALF + j], d);
    (mem ? g_De : g_Ds)[v1 * VOC + v2] = d;
    s_drow[mem][v2] = d;
    __syncthreads();

    const int l = tid & 63;
    if (l < HALF) {
        const float kl = (mem ? g_ke : g_ks)[v1 * HALF + l];
        const float iv = (mem ? g_inv_e : g_inv_s)[v1];
        ulonglong2 e;
        e.x = pack2(s_drow[mem][2 * l], s_drow[mem][2 * l + 1]);
        e.y = pack2(kl, iv);
        g_T[mem * (VOC * HALF) + v1 * HALF + l] = e;
    }
}

// ============================================================================
// Kernel B: backward adjoint scan, TOKEN-PAIR steps.
// Homogeneous recursion (query folded into S' init):
//   d_t = -S'_{t+1}[v_t],  dd_t = wiv_t d_t,  S'_t = S'_{t+1} + dd_t D[v_t,:]
//   S'_2048 = -Dq,  ctx = sum_t wkl_t d_t.
// Pair (a,b) = (t, t-1): both next-pair S lookups are shfl'd AFTER this
// pair's axpy (exact post-update reads -> NO cross-pair corrections); the
// only in-pair coupling is e_b = fma(dd_a, D[v_a,v_b], Rb). The 46-cyc
// SEL+SHFL+chain cycle is amortized over 2 tokens (~12.5 cyc/token).
// Signs folded into negated premultiplied weights (nwkl, nwiv).
//
// 256 threads: warp 0 = sem, warp 1 = epi; warps 2-7 preamble-only (exit).
// ============================================================================
__global__ void __launch_bounds__(256, 1) scan_kernel(
    const int* __restrict__ seq,
    const float* __restrict__ Wo,
    const float* __restrict__ bo,
    float* __restrict__ out)
{
    extern __shared__ int smem_raw[];
    int*        s_tokp = smem_raw;                         // 16 pad + 2048
    int*        s_tok  = s_tokp + 16;
    float*      s_D    = (float*)(s_tok + SEQLEN);         // 2 * 4096
    ulonglong2* s_T    = (ulonglong2*)(s_D + 2 * VOC * VOC); // 2*64*32 entries
    float*      s_ctx  = (float*)(s_T + 2 * VOC * HALF);   // 64

    const int b    = blockIdx.x;
    const int tid  = threadIdx.x;
    const int wid  = tid >> 5;
    const int mem  = wid & 1;                 // valid for wid 0,1
    const int lane = tid & 31;

    // ---- preamble: pure wide copies (8 warps cooperate) ----
    {
        const int4* seq4 = (const int4*)(seq + b * SEQLEN);
        int4* tok4 = (int4*)s_tok;
        #pragma unroll
        for (int i = tid; i < SEQLEN / 4; i += 256)
            tok4[i] = seq4[i];
        if (tid < 16) s_tokp[tid] = 0;        // pad: v = 0 (dead prefetch)

        float4* D4 = (float4*)s_D;
        const float4* gDs4 = (const float4*)g_Ds;
        const float4* gDe4 = (const float4*)g_De;
        #pragma unroll
        for (int i = tid; i < VOC * VOC / 4; i += 256) {
            D4[i]                 = gDs4[i];
            D4[VOC * VOC / 4 + i] = gDe4[i];
        }
        #pragma unroll
        for (int i = tid; i < 2 * VOC * HALF; i += 256)
            s_T[i] = g_T[i];
    }
    __syncthreads();

    if (wid >= 2) return;   // preamble helpers done (exited threads satisfy bar)

    const char* Db = (const char*)(s_D + mem * (VOC * VOC)); // + v*256 + v2*4
    const char* Tb = (const char*)(s_T + mem * (VOC * HALF)) + lane * 16; // + v*512

    // ---- prologue ----
    const int vq  = s_tok[2047];              // query token id (= pair-0 a)
    const int v46 = s_tok[2046];              // pair-0 b
    int o_a1 = s_tok[2045], o_b1 = s_tok[2044];   // pair 1
    int o_a2 = s_tok[2043], o_b2 = s_tok[2042];   // pair 2

    // S' init: S'_2048[v] = -D[v][vq]
    const char* Dqcol = Db + vq * 4;
    float Slo = -*(const float*)(Dqcol + (2 * lane) * 256);
    float Shi = -*(const float*)(Dqcol + (2 * lane + 1) * 256);

    // pair 0 = (2047 dummy, 2046)
    float Ra = 0.0f;                                          // unused (nwA=0)
    float Rb = -*(const float*)(Dqcol + v46 * 256);           // S'_2048[v46]
    float Dab = *(const float*)(Db + vq * 256 + v46 * 4);     // D[vq][v46]

    const ulonglong2 T47 = *(const ulonglong2*)(Tb + vq * 512);
    const ulonglong2 T46 = *(const ulonglong2*)(Tb + v46 * 512);
    float2 DrA = unpack2(T47.x);
    float2 DrB = unpack2(T46.x);

    const float wB0 = mem ? (2047.0f / 2048.0f) : 1.0f;
    float nwklA = 0.0f, nwivA = 0.0f;         // token 2047: dummy weight 0
    const float2 T46hi = unpack2(T46.y);
    float nwklB = -T46hi.x * wB0;
    float nwivB = -T46hi.y * wB0;

    // counters hold NEXT pair's negated weights (packed same value twice)
    u64 nwa2p, nwb2p, inc2p;
    if (mem) {
        nwa2p = pack2(-2046.0f / 2048.0f, -2046.0f / 2048.0f);
        nwb2p = pack2(-2045.0f / 2048.0f, -2045.0f / 2048.0f);
        inc2p = pack2(2.0f / 2048.0f, 2.0f / 2048.0f);
    } else {
        nwa2p = pack2(-1.0f, -1.0f);
        nwb2p = pack2(-1.0f, -1.0f);
        inc2p = 0ull;
    }

    ulonglong2 T_a1 = *(const ulonglong2*)(Tb + o_a1 * 512);  // pair-1 T
    ulonglong2 T_b1 = *(const ulonglong2*)(Tb + o_b1 * 512);

    int4 Q  = *(const int4*)(s_tok + 2040);   // tokens [2040..2043]
    int4 Qn = Q;
    const int* qptr = s_tok + 2036;           // next refill

    float ctx = 0.0f;

#define PSTEP(INSA, INSB, LOADQ) do {                                        \
    /* (1) current pair math (signs folded into negated premuls) */          \
    const float dd_a = nwivA * Ra;                                           \
    ctx = fmaf(Ra, nwklA, ctx);                                              \
    const float e_b = fmaf(dd_a, Dab, Rb);                                   \
    const float dd_b = nwivB * e_b;                                          \
    ctx = fmaf(e_b, nwklB, ctx);                                             \
    /* (2) axpy: S' += dd_a DrowA + dd_b DrowB */                            \
    Slo = fmaf(dd_a, DrA.x, Slo);                                            \
    Shi = fmaf(dd_a, DrA.y, Shi);                                            \
    Slo = fmaf(dd_b, DrB.x, Slo);                                            \
    Shi = fmaf(dd_b, DrB.y, Shi);                                            \
    /* (3) shfl lookups for NEXT pair (exact post-axpy reads) */             \
    const float sva = (o_a1 & 1) ? Shi : Slo;                                \
    const float svb = (o_b1 & 1) ? Shi : Slo;                                \
    const float Ra_n = __shfl_sync(0xffffffffu, sva, o_a1 >> 1);             \
    const float Rb_n = __shfl_sync(0xffffffffu, svb, o_b1 >> 1);             \
    if (LOADQ) { Qn = *(const int4*)qptr; qptr -= 4; }                       \
    /* (4) T prefetch for pair+2 (addresses 1 iter old) */                   \
    const ulonglong2 Ta_n = *(const ulonglong2*)(Tb + o_a2 * 512);           \
    const ulonglong2 Tb_n = *(const ulonglong2*)(Tb + o_b2 * 512);           \
    /* (5) in-pair D entry for next pair */                                  \
    const float Dab_n = *(const float*)(Db + o_a1 * 256 + o_b1 * 4);         \
    /* (6) premuls + Drows for next pair from last iter's T loads */         \
    const u64 wpa = mul2(T_a1.y, nwa2p);                                     \
    const u64 wpb = mul2(T_b1.y, nwb2p);                                     \
    nwa2p = add2(nwa2p, inc2p);                                              \
    nwb2p = add2(nwb2p, inc2p);                                              \
    const float2 wau = unpack2(wpa);                                         \
    const float2 wbu = unpack2(wpb);                                         \
    const float2 drA_n = unpack2(T_a1.x);                                    \
    const float2 drB_n = unpack2(T_b1.x);                                    \
    /* (7) rotate */                                                         \
    Ra = Ra_n; Rb = Rb_n; Dab = Dab_n;                                       \
    nwklA = wau.x; nwivA = wau.y;                                            \
    nwklB = wbu.x; nwivB = wbu.y;                                            \
    DrA = drA_n; DrB = drB_n;                                                \
    T_a1 = Ta_n; T_b1 = Tb_n;                                                \
    o_a1 = o_a2; o_b1 = o_b2;                                                \
    o_a2 = (INSA); o_b2 = (INSB);                                            \
} while (0)

    for (int it = 0; it < 1024; it += 2) {
        PSTEP(Q.y, Q.x, 1);      // even iter: inserts pair from Q.y/Q.x
        PSTEP(Qn.w, Qn.z, 0);    // odd iter
        Q = Qn;
    }
#undef PSTEP

    s_ctx[mem * HALF + lane] = ctx;
    __syncthreads();

    // out[b] = [ctx_s, ctx_e] @ Wo + bo   (64 threads, one column each)
    {
        float o = bo[tid];
        #pragma unroll
        for (int i = 0; i < 2 * HALF; i++)
            o = fmaf(s_ctx[i], Wo[i * VOC + tid], o);
        out[b * VOC + tid] = o;
    }
}

// ============================================================================
// Launch. Inputs in metadata order:
// 0:seq 1:embed 2:W1 3:b1 4:W2 5:b2 6:ln_g 7:ln_b 8:Ws 9:bs 10:We 11:be 12:Wo 13:bo
// ============================================================================
// Byte-accurate layout:
//   tok pad+ring: (16 + SEQLEN) * 4 =  8256
//   s_D:          2*VOC*VOC * 4     = 32768
//   s_T:          2*VOC*HALF * 16   = 65536
//   s_ctx:        VOC * 4           =   256
#define SCAN_SMEM_BYTES ((16 + SEQLEN) * 4 + 2*VOC*VOC*4 + 2*VOC*HALF*16 + VOC*4)

extern "C" void kernel_launch(void* const* d_in, const int* in_sizes, int n_in,
                              void* d_out, int out_size)
{
    const int*   seq   = (const int*)  d_in[0];
    const float* embed = (const float*)d_in[1];
    const float* W1    = (const float*)d_in[2];
    const float* b1    = (const float*)d_in[3];
    const float* W2    = (const float*)d_in[4];
    const float* b2    = (const float*)d_in[5];
    const float* ln_g  = (const float*)d_in[6];
    const float* ln_b  = (const float*)d_in[7];
    const float* Ws    = (const float*)d_in[8];
    const float* bs    = (const float*)d_in[9];
    const float* We    = (const float*)d_in[10];
    const float* be    = (const float*)d_in[11];
    const float* Wo    = (const float*)d_in[12];
    const float* bo    = (const float*)d_in[13];

    cudaFuncSetAttribute(scan_kernel,
                         cudaFuncAttributeMaxDynamicSharedMemorySize,
                         SCAN_SMEM_BYTES);

    precompute_kernel<<<VOC, 128>>>(embed, W1, b1, W2, b2, ln_g, ln_b,
                                    Ws, bs, We, be);
    dots_kernel<<<VOC, 128>>>();
    scan_kernel<<<BATCH, 256, SCAN_SMEM_BYTES>>>(seq, Wo, bo, (float*)d_out);
}